// round 6
// baseline (speedup 1.0000x reference)
#include <cuda_runtime.h>
#include <math.h>

// FineMatchingModule — algebraically collapsed (verified R3-R5, rel_err ~1.4e-8):
// both attention layers add only window-uniform shifts which the final softmax
// cancels. Per point:
//   corr[n] = sum_j s[j] * flat[n*256+j],  n = 0..24
// flat = channel-major-flattened zero-padded 5x5 window of target_features at
// the truncated coarse position; s = center pixel channel vector (= pixel 12).
// refined = pos + softmax(corr) @ offsets, offsets1d = linspace(-3,2,5).
//
// R6: 2 points / CTA (256 thr), float2 channel pairs (128 thr/point), ALL 25
// pixel loads issued before the single barrier (s is pixel 12 — no serial
// s->window round trip). No atomics, no shuffles in the reduction: per-thread
// dual accumulators (a 50-product run crosses <=1 token boundary) -> plain STS;
// static contiguous gather by one warp per point.

#define B_ 4
#define K_ 1024
#define H_ 256
#define W_ 256
#define C_ 256

__global__ __launch_bounds__(256, 4)
void fine_match_kernel(const float* __restrict__ tf,
                       const float* __restrict__ pos,
                       float* __restrict__ out)
{
    // per point: s (256 + 50 wrap), pa/pb partials
    __shared__ float s_sh[2][312];
    __shared__ float pa[2][128];
    __shared__ float pb[2][128];

    const int tid  = threadIdx.x;
    const int half = tid >> 7;             // point slot within CTA
    const int q    = tid & 127;            // thread-in-point; owns channels 2q, 2q+1
    const int pt   = (blockIdx.x << 1) | half;
    const int b    = pt >> 10;             // K = 1024

    const float pr = pos[2 * pt + 0];
    const float pc = pos[2 * pt + 1];
    const int r = (int)pr;                 // positions >= 0 -> trunc == astype(int32)
    const int c = (int)pc;

    const float* fb = tf + (size_t)b * (H_ * W_ * C_);

    // ---- Load all 25 window pixels (float2 per thread), center = pixel 12 ----
    float2 v[25];
    const bool interior = (r >= 2) & (r <= H_ - 3) & (c >= 2) & (c <= W_ - 3);
    if (interior) {
        const float2* base =
            (const float2*)(fb + ((size_t)(r - 2) * W_ + (c - 2)) * C_) + q;
        #pragma unroll
        for (int p = 0; p < 25; ++p) {
            const int off = (p / 5) * (W_ * (C_ / 2)) + (p % 5) * (C_ / 2);
            v[p] = base[off];              // coalesced 256B per warp
        }
    } else {
        #pragma unroll
        for (int p = 0; p < 25; ++p) {
            const int rr = r - 2 + p / 5;
            const int cc = c - 2 + p % 5;
            v[p] = make_float2(0.0f, 0.0f);
            if (rr >= 0 && rr < H_ && cc >= 0 && cc < W_)
                v[p] = ((const float2*)(fb + ((size_t)rr * W_ + cc) * C_))[q];
        }
    }

    // Stage center vector s (+ 50-entry wrap so product indices need no mask).
    s_sh[half][2 * q]     = v[12].x;
    s_sh[half][2 * q + 1] = v[12].y;
    if (q < 25) {                          // channels 0..49 duplicated at 256..305
        s_sh[half][256 + 2 * q]     = v[12].x;
        s_sh[half][256 + 2 * q + 1] = v[12].y;
    }
    __syncthreads();

    // ---- Products: idx = 50q + i, i = 0..49 (i = p for ch 2q, 25+p for 2q+1).
    // Token n = idx >> 8; at most one 256-boundary in the run -> 2 accumulators.
    const int sb    = (50 * q) & 255;
    const int split = 256 - sb;            // i >= split -> token n0+1

    float a0 = 0.0f, a1 = 0.0f;
    const float* s0 = &s_sh[half][sb];
    #pragma unroll
    for (int p = 0; p < 25; ++p) {
        const float t0 = v[p].x * s0[p];        // i = p
        const float t1 = v[p].y * s0[25 + p];   // i = 25 + p
        if (p < split)      a0 += t0; else a1 += t0;
        if (p + 25 < split) a0 += t1; else a1 += t1;
    }
    pa[half][q] = a0;                      // plain STS — no atomics
    pb[half][q] = a1;
    __syncthreads();

    // ---- One warp per point: static gather + softmax + expected offset ----
    if ((tid & 127) < 32) {                // warp 0 (point A), warp 4 (point B)
        const int lane = tid & 31;
        float logit = -INFINITY;
        if (lane < 25) {
            const int n  = lane;
            const int t0 = (256 * n + 49) / 50;   // first a0 contributor
            const int t1 = (256 * n + 255) / 50;  // last  a0 contributor (<=127)
            float sum = (n > 0) ? pb[half][t0 - 1] : 0.0f;
            #pragma unroll 6
            for (int t = t0; t <= t1; ++t) sum += pa[half][t];   // 5-6 iters
            logit = sum;
        }
        float m = logit;
        #pragma unroll
        for (int o = 16; o > 0; o >>= 1)
            m = fmaxf(m, __shfl_xor_sync(0xffffffffu, m, o));
        float e = (lane < 25) ? expf(logit - m) : 0.0f;
        float ssum = e;
        #pragma unroll
        for (int o = 16; o > 0; o >>= 1)
            ssum += __shfl_xor_sync(0xffffffffu, ssum, o);
        const float prb = e / ssum;        // 0 for lane >= 25

        // offsets: linspace(-3, 2, 5) = -3 + 1.25*i (exact fp32)
        const int ir = lane / 5;
        const int ic = lane - ir * 5;
        float dr = prb * (-3.0f + 1.25f * (float)ir);
        float dc = prb * (-3.0f + 1.25f * (float)ic);
        #pragma unroll
        for (int o = 16; o > 0; o >>= 1) {
            dr += __shfl_xor_sync(0xffffffffu, dr, o);
            dc += __shfl_xor_sync(0xffffffffu, dc, o);
        }
        if (lane == 0) {
            out[2 * pt + 0] = pr + dr;
            out[2 * pt + 1] = pc + dc;
        }
    }
}

extern "C" void kernel_launch(void* const* d_in, const int* in_sizes, int n_in,
                              void* d_out, int out_size)
{
    (void)in_sizes; (void)n_in; (void)out_size;
    // metadata order: 0=source_features (unused by reference), 1=target_features,
    // 2=coarse_positions, 3..6 = Wq,Wk,Wv,Wo (cancel algebraically)
    const float* tf  = (const float*)d_in[1];
    const float* pos = (const float*)d_in[2];
    float* out = (float*)d_out;

    fine_match_kernel<<<(B_ * K_) / 2, 256>>>(tf, pos, out);
}